// round 16
// baseline (speedup 1.0000x reference)
#include <cuda_runtime.h>
#include <cuda_fp16.h>

// AntiAliasInterpolation2d: depthwise 13x13 Gaussian, stride 4, zero pad 6.
// Input [32,3,512,512] f32, weight [3,1,13,13] f32, output [32,3,128,128] f32.
//
// Separable (exact): 2D kernel = outer(g,g), g[j] = k2[6][j]/sqrt(k2[6][6]).
// R16: SINGLE persistent kernel, grid-wide sense-reversing barrier between
// the horizontal and vertical phases. The fp16 intermediate is consumed
// immediately after being produced -> L2-resident (no DRAM round-trip, which
// R15 metrics proved was costing vpass ~2x). 768 CTAs, launch_bounds(256,6)
// guarantees 888 resident slots >= grid (no deadlock). Barrier state is
// sense-reversing -> safe across CUDA-graph replays.

#define IW    512
#define IW4   128                // input row in float4
#define OW    128
#define PROWS 532                // 6 pad + 512 + 14 pad rows per image
#define GRID  768

__device__ __half g_tmp[96 * PROWS * OW];   // 13.1 MB scratch
__device__ unsigned bar_cnt   = 0;
__device__ unsigned bar_sense = 0;

__device__ __forceinline__ float4 ldcs4(const float4* p) { return __ldcs(p); }

__global__ __launch_bounds__(256, 6)
void aa_fused_kernel(const float* __restrict__ inp,
                     const float* __restrict__ w,
                     float* __restrict__ out)
{
    const int tid  = threadIdx.x;
    const int lane = tid & 31;
    const int wid  = tid >> 5;

    // Read barrier sense BEFORE arriving (per-launch target; replay-safe).
    __shared__ unsigned s_target;
    if (tid == 0) s_target = (*(volatile unsigned*)&bar_sense) ^ 1u;

    // ---- pad zeroing: 96 images * 20 pad rows * 64 u32 ----
    {
        const int gtid = blockIdx.x * 256 + tid;
        if (gtid < 96 * 20 * 64) {
            const int img  = gtid / (20 * 64);
            const int rem  = gtid - img * (20 * 64);
            const int prow = rem >> 6;                       // 0..19
            const int col  = rem & 63;
            const int rr   = (prow < 6) ? prow : (512 + prow);
            reinterpret_cast<unsigned*>(g_tmp)[((size_t)img * PROWS + rr) * 64 + col] = 0u;
        }
    }

    // ================= phase 1: horizontal (4 units per CTA) =================
#pragma unroll 1
    for (int u = 0; u < 4; u++) {
        const int unit = blockIdx.x + GRID * u;   // 0..3071
        const int wg = unit * 8 + wid;            // 256 row-pairs per image
        const int nc = wg >> 8;
        const int r0 = 2 * (wg & 255);            // rows r0, r0+1 within image
        const int c  = nc % 3;

        float g[7];
        {
            const float inv = 1.0f / sqrtf(w[c * 169 + 84]);
#pragma unroll
            for (int q = 0; q < 7; q++) g[q] = w[c * 169 + 78 + q] * inv;
        }

        const float4* ra = reinterpret_cast<const float4*>(inp)
                         + ((size_t)nc * IW + r0) * IW4;
        const float4* rb = ra + IW4;
        __half* da = g_tmp + ((size_t)nc * PROWS + 6 + r0) * OW;

        const float4 z4 = make_float4(0.f, 0.f, 0.f, 0.f);

#pragma unroll
        for (int j = 0; j < 4; j++) {
            const int ox = lane + 32 * j;
            float4 a0 = (ox >= 2)       ? ldcs4(ra + ox - 2) : z4;
            float4 a1 = (ox >= 1)       ? ldcs4(ra + ox - 1) : z4;
            float4 a2 =                   ldcs4(ra + ox);
            float4 a3 = (ox <= IW4 - 2) ? ldcs4(ra + ox + 1) : z4;
            float4 b0 = (ox >= 2)       ? ldcs4(rb + ox - 2) : z4;
            float4 b1 = (ox >= 1)       ? ldcs4(rb + ox - 1) : z4;
            float4 b2 =                   ldcs4(rb + ox);
            float4 b3 = (ox <= IW4 - 2) ? ldcs4(rb + ox + 1) : z4;

            float e0 =       g[0] * a0.z;
            float e1 =       g[1] * a0.w;
            e0 = fmaf(g[2], a1.x, e0);
            e1 = fmaf(g[3], a1.y, e1);
            e0 = fmaf(g[4], a1.z, e0);
            e1 = fmaf(g[5], a1.w, e1);
            e0 = fmaf(g[6], a2.x, e0);
            e1 = fmaf(g[5], a2.y, e1);
            e0 = fmaf(g[4], a2.z, e0);
            e1 = fmaf(g[3], a2.w, e1);
            e0 = fmaf(g[2], a3.x, e0);
            e1 = fmaf(g[1], a3.y, e1);
            e0 = fmaf(g[0], a3.z, e0);

            float f0 =       g[0] * b0.z;
            float f1 =       g[1] * b0.w;
            f0 = fmaf(g[2], b1.x, f0);
            f1 = fmaf(g[3], b1.y, f1);
            f0 = fmaf(g[4], b1.z, f0);
            f1 = fmaf(g[5], b1.w, f1);
            f0 = fmaf(g[6], b2.x, f0);
            f1 = fmaf(g[5], b2.y, f1);
            f0 = fmaf(g[4], b2.z, f0);
            f1 = fmaf(g[3], b2.w, f1);
            f0 = fmaf(g[2], b3.x, f0);
            f1 = fmaf(g[1], b3.y, f1);
            f0 = fmaf(g[0], b3.z, f0);

            da[ox]      = __float2half_rn(e0 + e1);
            da[OW + ox] = __float2half_rn(f0 + f1);
        }
    }

    // ================= grid-wide barrier (sense-reversing) =================
    __threadfence();                 // tmp stores visible device-wide
    __syncthreads();
    if (tid == 0) {
        const unsigned target = s_target;
        const unsigned t = atomicAdd(&bar_cnt, 1u);
        if (t == GRID - 1) {
            atomicExch(&bar_cnt, 0u);                    // reset for next launch
            __threadfence();
            *(volatile unsigned*)&bar_sense = target;    // release
        } else {
            while ((*(volatile unsigned*)&bar_sense) != target) __nanosleep(64);
            __threadfence();                             // acquire
        }
    }
    __syncthreads();

    // ================= phase 2: vertical (1 unit per CTA) =================
    {
        const int idx = blockIdx.x * 256 + tid;   // 0..196607
        const int ox4 = idx & 31;                 // float4 column group
        const int t2  = idx >> 5;                 // nc*64 + oyp (warp-uniform)
        const int oyp = t2 & 63;
        const int nc  = t2 >> 6;
        const int oy0 = 2 * oyp;
        const int c   = nc % 3;

        float g[7];
        {
            const float inv = 1.0f / sqrtf(w[c * 169 + 84]);
#pragma unroll
            for (int q = 0; q < 7; q++) g[q] = w[c * 169 + 78 + q] * inv;
        }

        const uint2* base = reinterpret_cast<const uint2*>(
                                g_tmp + ((size_t)nc * PROWS + 6) * OW) + ox4;
        const int ib = 8 * oyp - 6;               // first window row of out0

        float4 p0 = make_float4(0.f, 0.f, 0.f, 0.f);
        float4 p1 = make_float4(0.f, 0.f, 0.f, 0.f);
#pragma unroll
        for (int k = 0; k < 17; k++) {
            uint2 raw = base[(ptrdiff_t)(ib + k) * 32];
            float2 f01 = __half22float2(*reinterpret_cast<__half2*>(&raw.x));
            float2 f23 = __half22float2(*reinterpret_cast<__half2*>(&raw.y));
            if (k <= 12) {
                const float gk = g[k < 7 ? k : 12 - k];
                p0.x = fmaf(gk, f01.x, p0.x);
                p0.y = fmaf(gk, f01.y, p0.y);
                p0.z = fmaf(gk, f23.x, p0.z);
                p0.w = fmaf(gk, f23.y, p0.w);
            }
            if (k >= 4) {
                const int m = k - 4;
                const float gm = g[m < 7 ? m : 12 - m];
                p1.x = fmaf(gm, f01.x, p1.x);
                p1.y = fmaf(gm, f01.y, p1.y);
                p1.z = fmaf(gm, f23.x, p1.z);
                p1.w = fmaf(gm, f23.y, p1.w);
            }
        }
        float4* ob = reinterpret_cast<float4*>(out)
                   + ((size_t)nc * 128 + oy0) * 32 + ox4;
        ob[0]  = p0;
        ob[32] = p1;
    }
}

extern "C" void kernel_launch(void* const* d_in, const int* in_sizes, int n_in,
                              void* d_out, int out_size)
{
    const float* inp = (const float*)d_in[0];   // [32,3,512,512]
    const float* wgt = (const float*)d_in[1];   // [3,1,13,13]
    float* out = (float*)d_out;                 // [32,3,128,128]

    aa_fused_kernel<<<GRID, 256>>>(inp, wgt, out);
}

// round 17
// speedup vs baseline: 1.1070x; 1.1070x over previous
#include <cuda_runtime.h>
#include <cuda_fp16.h>

// AntiAliasInterpolation2d: depthwise 13x13 Gaussian, stride 4, zero pad 6.
// Input [32,3,512,512] f32, weight [3,1,13,13] f32, output [32,3,128,128] f32.
//
// Separable (exact): 2D kernel = outer(g,g), g[j] = k2[6][j]/sqrt(k2[6][6]).
// R17: fused kernel with PER-IMAGE 8-CTA CLUSTERS. Each cluster produces and
// consumes one image's fp16 intermediate (L2-resident, proven in R16), with a
// hardware cluster barrier instead of R16's grid-wide software barrier (whose
// slowest-of-768 tail cost ~4us). 96 independent clusters -> no global tail.

#define IW    512
#define IW4   128                // input row in float4
#define OW    128
#define PROWS 532                // 6 pad + 512 + 14 pad rows per image

__device__ __half g_tmp[96 * PROWS * OW];   // 13.1 MB scratch

__device__ __forceinline__ float4 ldcs4(const float4* p) { return __ldcs(p); }

__global__ __launch_bounds__(256, 6) __cluster_dims__(8, 1, 1)
void aa_fused_kernel(const float* __restrict__ inp,
                     const float* __restrict__ w,
                     float* __restrict__ out)
{
    const int tid  = threadIdx.x;
    const int lane = tid & 31;
    const int wid  = tid >> 5;

    const int nc   = blockIdx.x >> 3;         // image id = cluster id
    const int rank = blockIdx.x & 7;          // rank within cluster
    const int c    = nc % 3;

    float g[7];
    {
        const float inv = 1.0f / sqrtf(w[c * 169 + 84]);
#pragma unroll
        for (int q = 0; q < 7; q++) g[q] = w[c * 169 + 78 + q] * inv;
    }

    // ---- pad zeroing for this image: 20 rows * 64 u32 = 1280 words ----
    {
        const int t2 = rank * 256 + tid;      // 0..2047
        if (t2 < 20 * 64) {
            const int prow = t2 >> 6;         // 0..19
            const int col  = t2 & 63;
            const int rr   = (prow < 6) ? prow : (512 + prow);
            reinterpret_cast<unsigned*>(g_tmp)[((size_t)nc * PROWS + rr) * 64 + col] = 0u;
        }
    }

    // ========== phase 1: horizontal — 4 row-pair units per warp ==========
    const float4* img4 = reinterpret_cast<const float4*>(inp) + (size_t)nc * (IW * IW4);
    __half* timg = g_tmp + ((size_t)nc * PROWS + 6) * OW;
    const float4 z4 = make_float4(0.f, 0.f, 0.f, 0.f);

#pragma unroll 1
    for (int u = 0; u < 4; u++) {
        const int p  = rank * 32 + u * 8 + wid;   // row-pair 0..255
        const int r0 = 2 * p;
        const float4* ra = img4 + (size_t)r0 * IW4;
        const float4* rb = ra + IW4;
        __half* da = timg + (size_t)r0 * OW;

#pragma unroll
        for (int j = 0; j < 4; j++) {
            const int ox = lane + 32 * j;
            float4 a0 = (ox >= 2)       ? ldcs4(ra + ox - 2) : z4;
            float4 a1 = (ox >= 1)       ? ldcs4(ra + ox - 1) : z4;
            float4 a2 =                   ldcs4(ra + ox);
            float4 a3 = (ox <= IW4 - 2) ? ldcs4(ra + ox + 1) : z4;
            float4 b0 = (ox >= 2)       ? ldcs4(rb + ox - 2) : z4;
            float4 b1 = (ox >= 1)       ? ldcs4(rb + ox - 1) : z4;
            float4 b2 =                   ldcs4(rb + ox);
            float4 b3 = (ox <= IW4 - 2) ? ldcs4(rb + ox + 1) : z4;

            float e0 =       g[0] * a0.z;
            float e1 =       g[1] * a0.w;
            e0 = fmaf(g[2], a1.x, e0);
            e1 = fmaf(g[3], a1.y, e1);
            e0 = fmaf(g[4], a1.z, e0);
            e1 = fmaf(g[5], a1.w, e1);
            e0 = fmaf(g[6], a2.x, e0);
            e1 = fmaf(g[5], a2.y, e1);
            e0 = fmaf(g[4], a2.z, e0);
            e1 = fmaf(g[3], a2.w, e1);
            e0 = fmaf(g[2], a3.x, e0);
            e1 = fmaf(g[1], a3.y, e1);
            e0 = fmaf(g[0], a3.z, e0);

            float f0 =       g[0] * b0.z;
            float f1 =       g[1] * b0.w;
            f0 = fmaf(g[2], b1.x, f0);
            f1 = fmaf(g[3], b1.y, f1);
            f0 = fmaf(g[4], b1.z, f0);
            f1 = fmaf(g[5], b1.w, f1);
            f0 = fmaf(g[6], b2.x, f0);
            f1 = fmaf(g[5], b2.y, f1);
            f0 = fmaf(g[4], b2.z, f0);
            f1 = fmaf(g[3], b2.w, f1);
            f0 = fmaf(g[2], b3.x, f0);
            f1 = fmaf(g[1], b3.y, f1);
            f0 = fmaf(g[0], b3.z, f0);

            da[ox]      = __float2half_rn(e0 + e1);
            da[OW + ox] = __float2half_rn(f0 + f1);
        }
    }

    // ========== cluster barrier: this image's tmp fully written ==========
    __threadfence();                          // release tmp stores (gpu scope)
    asm volatile("barrier.cluster.arrive.aligned;" ::: "memory");
    asm volatile("barrier.cluster.wait.aligned;" ::: "memory");
    __threadfence();                          // acquire

    // ========== phase 2: vertical — warp = one oy-pair of this image ==========
    {
        const int oyp = rank * 8 + wid;       // 0..63
        const int ox4 = lane;                 // float4 column group 0..31
        const int oy0 = 2 * oyp;

        const uint2* base = reinterpret_cast<const uint2*>(
                                g_tmp + ((size_t)nc * PROWS + 6) * OW) + ox4;
        const int ib = 8 * oyp - 6;           // first window row of out0

        float4 p0 = make_float4(0.f, 0.f, 0.f, 0.f);
        float4 p1 = make_float4(0.f, 0.f, 0.f, 0.f);
#pragma unroll
        for (int k = 0; k < 17; k++) {
            uint2 raw = base[(ptrdiff_t)(ib + k) * 32];
            float2 f01 = __half22float2(*reinterpret_cast<__half2*>(&raw.x));
            float2 f23 = __half22float2(*reinterpret_cast<__half2*>(&raw.y));
            if (k <= 12) {
                const float gk = g[k < 7 ? k : 12 - k];
                p0.x = fmaf(gk, f01.x, p0.x);
                p0.y = fmaf(gk, f01.y, p0.y);
                p0.z = fmaf(gk, f23.x, p0.z);
                p0.w = fmaf(gk, f23.y, p0.w);
            }
            if (k >= 4) {
                const int m = k - 4;
                const float gm = g[m < 7 ? m : 12 - m];
                p1.x = fmaf(gm, f01.x, p1.x);
                p1.y = fmaf(gm, f01.y, p1.y);
                p1.z = fmaf(gm, f23.x, p1.z);
                p1.w = fmaf(gm, f23.y, p1.w);
            }
        }
        float4* ob = reinterpret_cast<float4*>(out)
                   + ((size_t)nc * 128 + oy0) * 32 + ox4;
        ob[0]  = p0;
        ob[32] = p1;
    }
}

extern "C" void kernel_launch(void* const* d_in, const int* in_sizes, int n_in,
                              void* d_out, int out_size)
{
    const float* inp = (const float*)d_in[0];   // [32,3,512,512]
    const float* wgt = (const float*)d_in[1];   // [3,1,13,13]
    float* out = (float*)d_out;                 // [32,3,128,128]

    aa_fused_kernel<<<768, 256>>>(inp, wgt, out);   // 96 clusters of 8 CTAs
}